// round 15
// baseline (speedup 1.0000x reference)
#include <cuda_runtime.h>
#include <cuda_bf16.h>
#include <math.h>
#include <stdint.h>

#define NN     20000
#define EE     320000
#define RNA    2000
#define PROT   100
#define EMB    256
#define HID    128
#define NHEAD  4
#define HD     512
#define INF    2100
#define NEG_SLOPE 0.2f

#define MPAD   20096
#define MTILES 157

#define KCH         32
#define STAGES      3
#define STAGE_BYTES 32768                        // Ah,Al,Bh,Bl x 8KB
#define GEMM_SMEM   (STAGES * STAGE_BYTES + 128) // + full/empty mbarriers
#define GTHREADS    512

// ---------------- device scratch (zero-init at load) ----------------
// bf16 hi/lo buffers use TILED layout:
//   [row_tile][k_chunk][8192B swizzled block]  (block = 128 rows x 32 cols SW64)
__device__ __align__(16) __nv_bfloat16 g_xr_h[(size_t)MPAD * 2048];
__device__ __align__(16) __nv_bfloat16 g_xr_l[(size_t)MPAD * 2048];
__device__ __align__(16) __nv_bfloat16 g_xp_h[(size_t)MPAD * 128];
__device__ __align__(16) __nv_bfloat16 g_xp_l[(size_t)MPAD * 128];
__device__ __align__(16) __nv_bfloat16 g_hh[(size_t)MPAD * 512];
__device__ __align__(16) __nv_bfloat16 g_hl[(size_t)MPAD * 512];
__device__ __align__(16) __nv_bfloat16 g_eh[(size_t)MPAD * 128];
__device__ __align__(16) __nv_bfloat16 g_el[(size_t)MPAD * 128];
__device__ __align__(16) __nv_bfloat16 g_rdh[(size_t)MPAD * 512];
__device__ __align__(16) __nv_bfloat16 g_rdl[(size_t)MPAD * 512];

__device__ __align__(16) float g_xslin[(size_t)MPAD * 1024];
__device__ __align__(16) float g_asrc[(size_t)NN * NHEAD];
__device__ __align__(16) float g_adst[(size_t)NN * NHEAD];
__device__ __align__(16) float g_wp1[8 * 512];
__device__ __align__(16) float g_wp2[8 * 512];
__device__ __align__(16) float g_bcat1[1024];
__device__ __align__(16) float g_bcat2[1024];
__device__ __align__(16) float g_bcatd[512];

__device__ __align__(16) __nv_bfloat16 g_wr_h[256 * 2048],   g_wr_l[256 * 2048];
__device__ __align__(16) __nv_bfloat16 g_wp_h[256 * 128],    g_wp_l[256 * 128];
__device__ __align__(16) __nv_bfloat16 g_wc1_h[1024 * 512],  g_wc1_l[1024 * 512];
__device__ __align__(16) __nv_bfloat16 g_wc2_h[1024 * 512],  g_wc2_l[1024 * 512];
__device__ __align__(16) __nv_bfloat16 g_wagg_h[128 * 512],  g_wagg_l[128 * 512];
__device__ __align__(16) __nv_bfloat16 g_wdc_h[512 * 128],   g_wdc_l[512 * 128];
__device__ __align__(16) __nv_bfloat16 g_wrr_h[2048 * 256],  g_wrr_l[2048 * 256];
__device__ __align__(16) __nv_bfloat16 g_wrp_h[128 * 256],   g_wrp_l[128 * 256];

__device__ int g_deg[NN];
__device__ int g_cursor[NN];
__device__ int g_rowptr[NN + 1];
__device__ int g_csr[EE];

// ---------------- PTX helpers ----------------
__device__ __forceinline__ uint32_t smem_u32(const void* p) {
    uint32_t a;
    asm("{ .reg .u64 t; cvta.to.shared.u64 t, %1; cvt.u32.u64 %0, t; }" : "=r"(a) : "l"(p));
    return a;
}
__device__ __forceinline__ void bulk8k(uint32_t dst, const void* src, uint32_t mbar) {
    asm volatile(
        "cp.async.bulk.shared::cta.global.mbarrier::complete_tx::bytes [%0], [%1], %2, [%3];"
        :: "r"(dst), "l"(src), "r"(8192), "r"(mbar) : "memory");
}
#define MBAR_INIT(a, c) \
    asm volatile("mbarrier.init.shared.b64 [%0], %1;" :: "r"(a), "r"(c) : "memory")
#define MBAR_EXPECT(a, tx) \
    asm volatile("mbarrier.arrive.expect_tx.shared.b64 _, [%0], %1;" :: "r"(a), "r"(tx) : "memory")
#define MBAR_ARRIVE(a) \
    asm volatile("mbarrier.arrive.shared.b64 _, [%0];" :: "r"(a) : "memory")
__device__ __forceinline__ void mbar_wait(uint32_t a, int par) {
    asm volatile(
        "{\n\t.reg .pred P;\n\t"
        "W_%=:\n\t"
        "mbarrier.try_wait.parity.acquire.cta.shared::cta.b64 P, [%0], %1, 0x989680;\n\t"
        "@P bra.uni D_%=;\n\t"
        "bra.uni W_%=;\n\t"
        "D_%=:\n\t}"
        :: "r"(a), "r"(par) : "memory");
}

__device__ __forceinline__ uint32_t swz64(uint32_t off) {
    return off ^ ((off >> 3) & 0x30);
}
__device__ __forceinline__ size_t toff(int row, int k, int chTot) {
    return ((size_t)((row >> 7) * chTot + (k >> 5))) * 8192
         + swz64((uint32_t)((row & 127) * 64 + (k & 31) * 2));
}
__device__ __forceinline__ void ldm_x4(uint32_t addr, uint32_t r[4]) {
    asm volatile("ldmatrix.sync.aligned.m8n8.x4.shared.b16 {%0,%1,%2,%3}, [%4];"
                 : "=r"(r[0]), "=r"(r[1]), "=r"(r[2]), "=r"(r[3]) : "r"(addr));
}
__device__ __forceinline__ void mma_bf16(float c[4], const uint32_t a[4],
                                         uint32_t b0, uint32_t b1) {
    asm volatile(
        "mma.sync.aligned.m16n8k16.row.col.f32.bf16.bf16.f32 "
        "{%0,%1,%2,%3}, {%4,%5,%6,%7}, {%8,%9}, {%0,%1,%2,%3};"
        : "+f"(c[0]), "+f"(c[1]), "+f"(c[2]), "+f"(c[3])
        : "r"(a[0]), "r"(a[1]), "r"(a[2]), "r"(a[3]), "r"(b0), "r"(b1));
}
__device__ __forceinline__ uint32_t pack_bf16x2(float a, float b) {
    __nv_bfloat162 t = __floats2bfloat162_rn(a, b);
    return *(uint32_t*)&t;
}

// ---------------- warp-MMA GEMM (bulk, decoupled warps, A-resident) -------
// Per chunk per warp: 16 LDSM.x4 (4 A + 4 B per ks), 48 MMA.
// Swizzle composition: offset = swz64(row*64) ^ (kb + khalf*16)  [XOR, not +:
// mask bits 4-5 overlap low bits 4-5; addition would carry -> wrong address]
__global__ void __launch_bounds__(GTHREADS, 2)
tc_gemm(const char* __restrict__ Ah, const char* __restrict__ Al, int aChTot, int aChOff,
        const char* __restrict__ Bh, const char* __restrict__ Bl, int bChTot,
        float* __restrict__ C, int ldc,
        char* __restrict__ Chi, char* __restrict__ Clo, int oChTot, int oColBase,
        int M, int N, int nchunks,
        const float* __restrict__ bias1, const float* __restrict__ bias2, int relu)
{
    extern __shared__ char smem[];
    const uint32_t sm = smem_u32(smem);
    const uint32_t mbF = sm + STAGES * STAGE_BYTES;        // full[0..2]
    const uint32_t mbE = mbF + 8 * STAGES;                 // empty[0..2]
    const int tid = threadIdx.x;
    const int wid = tid >> 5, lane = tid & 31;
    const int row0 = blockIdx.y * 128;
    const int col0 = blockIdx.x * 128;

    const int wm = wid & 3;
    const int wn = wid >> 2;
    const int li    = lane & 7;
    const int matm  = (lane >> 3) & 1;
    const int khalf = lane >> 4;

    // swizzled row-base offsets (low 6 bits of argument are zero here)
    uint32_t aswz[2], bswz[2];
#pragma unroll
    for (int mi = 0; mi < 2; mi++)
        aswz[mi] = swz64((uint32_t)((wm * 32 + mi * 16 + matm * 8 + li) * 64));
#pragma unroll
    for (int nj = 0; nj < 2; nj++)
        bswz[nj] = swz64((uint32_t)((wn * 32 + nj * 16 + matm * 8 + li) * 64));
    const uint32_t klow = (uint32_t)(khalf * 16);

    const size_t aBase = (size_t)(blockIdx.y * aChTot + aChOff) * 8192;
    const size_t bBase = (size_t)(blockIdx.x * bChTot) * 8192;

    float acc[2][4][4];
#pragma unroll
    for (int a = 0; a < 2; a++)
#pragma unroll
        for (int b = 0; b < 4; b++)
#pragma unroll
            for (int c = 0; c < 4; c++) acc[a][b][c] = 0.f;

    if (tid == 0) {
#pragma unroll
        for (int s = 0; s < STAGES; s++) {
            MBAR_INIT(mbF + 8 * s, 1);
            MBAR_INIT(mbE + 8 * s, 16);
        }
    }
    __syncthreads();

#define LOADC(cc) do { \
    const int s_ = (cc) % STAGES; \
    const uint32_t st_ = sm + (uint32_t)s_ * STAGE_BYTES; \
    const uint32_t mb_ = mbF + 8 * s_; \
    MBAR_EXPECT(mb_, STAGE_BYTES); \
    bulk8k(st_,         Ah + aBase + (size_t)(cc) * 8192, mb_); \
    bulk8k(st_ + 8192,  Al + aBase + (size_t)(cc) * 8192, mb_); \
    bulk8k(st_ + 16384, Bh + bBase + (size_t)(cc) * 8192, mb_); \
    bulk8k(st_ + 24576, Bl + bBase + (size_t)(cc) * 8192, mb_); \
} while (0)

    if (tid == 0) {
        for (int c = 0; c < 2 && c < nchunks; c++) LOADC(c);
    }

    for (int c = 0; c < nchunks; c++) {
        const int s = c % STAGES;
        const uint32_t sb = sm + (uint32_t)s * STAGE_BYTES;

        if (tid == 0 && c + 2 < nchunks) {
            if (c >= 1) mbar_wait(mbE + 8 * ((c + 2) % STAGES), ((c - 1) / STAGES) & 1);
            LOADC(c + 2);
        }
        mbar_wait(mbF + 8 * s, (c / STAGES) & 1);

#pragma unroll
        for (int ks = 0; ks < 2; ks++) {
            const uint32_t lowo = (uint32_t)(ks * 32) | klow;   // bits 4-5 only
            uint32_t ah[2][4], al[2][4];
            ldm_x4(sb + (aswz[0] ^ lowo), ah[0]);
            ldm_x4(sb + (aswz[1] ^ lowo), ah[1]);
            ldm_x4(sb + 8192 + (aswz[0] ^ lowo), al[0]);
            ldm_x4(sb + 8192 + (aswz[1] ^ lowo), al[1]);
#pragma unroll
            for (int nj = 0; nj < 2; nj++) {
                uint32_t b[4];
                ldm_x4(sb + 16384 + (bswz[nj] ^ lowo), b);   // Bh
#pragma unroll
                for (int mi = 0; mi < 2; mi++)
#pragma unroll
                    for (int s2 = 0; s2 < 2; s2++) {
                        mma_bf16(acc[mi][nj * 2 + s2], ah[mi], b[s2], b[s2 + 2]);
                        mma_bf16(acc[mi][nj * 2 + s2], al[mi], b[s2], b[s2 + 2]);
                    }
                ldm_x4(sb + 24576 + (bswz[nj] ^ lowo), b);   // Bl
#pragma unroll
                for (int mi = 0; mi < 2; mi++)
#pragma unroll
                    for (int s2 = 0; s2 < 2; s2++)
                        mma_bf16(acc[mi][nj * 2 + s2], ah[mi], b[s2], b[s2 + 2]);
            }
        }
        if (lane == 0) MBAR_ARRIVE(mbE + 8 * s);
    }
#undef LOADC

    // epilogue: acc -> smem fp32 (stride 132) -> coalesced global
    __syncthreads();
    float* eps = (float*)smem;
    const int grp = lane >> 2, qp = lane & 3;
#pragma unroll
    for (int mi = 0; mi < 2; mi++) {
#pragma unroll
        for (int ni = 0; ni < 4; ni++) {
            const int r = wm * 32 + mi * 16 + grp;
            const int col = wn * 32 + ni * 8 + qp * 2;
            eps[r * 132 + col]           = acc[mi][ni][0];
            eps[r * 132 + col + 1]       = acc[mi][ni][1];
            eps[(r + 8) * 132 + col]     = acc[mi][ni][2];
            eps[(r + 8) * 132 + col + 1] = acc[mi][ni][3];
        }
    }
    __syncthreads();

#pragma unroll
    for (int i = 0; i < 8; i++) {
        const int f = tid + i * GTHREADS;
        const int r = f >> 5, c4 = f & 31;
        const int grow = row0 + r;
        const int col = col0 + c4 * 4;
        if (grow >= M || col >= N) continue;
        float v[4];
#pragma unroll
        for (int j = 0; j < 4; j++) {
            v[j] = eps[r * 132 + c4 * 4 + j];
            const int cc = col + j;
            if (cc < N) {
                if (bias1) v[j] += bias1[cc];
                if (bias2) v[j] += bias2[cc];
                if (relu)  v[j] = fmaxf(v[j], 0.f);
            }
        }
        if (C) {
            if (col + 3 < N) {
                *(float4*)(C + (size_t)grow * ldc + col) = make_float4(v[0], v[1], v[2], v[3]);
            } else {
#pragma unroll
                for (int j = 0; j < 4; j++)
                    if (col + j < N) C[(size_t)grow * ldc + col + j] = v[j];
            }
        }
        if (Chi) {
            __nv_bfloat16 h[4];
            float lo[4];
#pragma unroll
            for (int j = 0; j < 4; j++) {
                h[j] = __float2bfloat16(v[j]);
                lo[j] = v[j] - __bfloat162float(h[j]);
            }
            uint32_t h01 = ((uint32_t)(*(uint16_t*)&h[1]) << 16) | (*(uint16_t*)&h[0]);
            uint32_t h23 = ((uint32_t)(*(uint16_t*)&h[3]) << 16) | (*(uint16_t*)&h[2]);
            uint32_t l01 = pack_bf16x2(lo[0], lo[1]);
            uint32_t l23 = pack_bf16x2(lo[2], lo[3]);
            size_t o = toff(grow, oColBase + col, oChTot);
            *(uint2*)(Chi + o) = make_uint2(h01, h23);
            *(uint2*)(Clo + o) = make_uint2(l01, l23);
        }
    }
}

// ---------------- conversions / small kernels ----------------
__global__ void splitx_kernel(const float* __restrict__ x, int lda, int colOff,
                              int M, int K, int chTot,
                              char* __restrict__ h, char* __restrict__ l)
{
    const int qpr = chTot * 8;
    long idx = (long)blockIdx.x * blockDim.x + threadIdx.x;
    long total = (long)MPAD * qpr;
    if (idx >= total) return;
    int row = (int)(idx / qpr);
    int k = (int)(idx % qpr) * 4;
    float f[4];
#pragma unroll
    for (int j = 0; j < 4; j++) {
        int kk = k + j;
        f[j] = (row < M && kk < K) ? x[(size_t)row * lda + colOff + kk] : 0.f;
    }
    __nv_bfloat16 h0 = __float2bfloat16(f[0]);
    __nv_bfloat16 h1 = __float2bfloat16(f[1]);
    __nv_bfloat16 h2 = __float2bfloat16(f[2]);
    __nv_bfloat16 h3 = __float2bfloat16(f[3]);
    uint32_t hi01 = ((uint32_t)(*(uint16_t*)&h1) << 16) | (*(uint16_t*)&h0);
    uint32_t hi23 = ((uint32_t)(*(uint16_t*)&h3) << 16) | (*(uint16_t*)&h2);
    uint32_t lo01 = pack_bf16x2(f[0] - __bfloat162float(h0), f[1] - __bfloat162float(h1));
    uint32_t lo23 = pack_bf16x2(f[2] - __bfloat162float(h2), f[3] - __bfloat162float(h3));
    size_t o = toff(row, k, chTot);
    *(uint2*)(h + o) = make_uint2(hi01, hi23);
    *(uint2*)(l + o) = make_uint2(lo01, lo23);
}

__global__ void tsplit_kernel(const float* __restrict__ W, int K, int N,
                              int Kpad, int Npad,
                              char* __restrict__ h, char* __restrict__ l)
{
    long idx = (long)blockIdx.x * blockDim.x + threadIdx.x;
    long total = (long)Npad * Kpad;
    if (idx >= total) return;
    int n = (int)(idx / Kpad);
    int k = (int)(idx % Kpad);
    float v = 0.f;
    if (n < N && k < K) v = W[(size_t)k * N + n];
    __nv_bfloat16 hi = __float2bfloat16(v);
    __nv_bfloat16 lo = __float2bfloat16(v - __bfloat162float(hi));
    size_t o = toff(n, k, Kpad / 32);
    *(__nv_bfloat16*)(h + o) = hi;
    *(__nv_bfloat16*)(l + o) = lo;
}

__global__ void prep_layer_kernel(const float* __restrict__ ws, const float* __restrict__ lw,
                                  const float* __restrict__ lb, const float* __restrict__ gb,
                                  char* __restrict__ h, char* __restrict__ l,
                                  float* __restrict__ bias)
{
    long idx = (long)blockIdx.x * blockDim.x + threadIdx.x;
    const long total = 1024L * 512;
    if (idx < total) {
        int n = (int)(idx / 512);
        int k = (int)(idx % 512);
        float v = (n < 512) ? ws[(size_t)k * 512 + n] : lw[(size_t)k * 512 + (n - 512)];
        __nv_bfloat16 hi = __float2bfloat16(v);
        __nv_bfloat16 lo = __float2bfloat16(v - __bfloat162float(hi));
        size_t o = toff(n, k, 16);
        *(__nv_bfloat16*)(h + o) = hi;
        *(__nv_bfloat16*)(l + o) = lo;
    } else {
        long j = idx - total;
        if (j < 512) bias[j] = 0.f;
        else if (j < 1024) bias[j] = lb[j - 512] + gb[j - 512];
    }
}

__global__ void wproj_kernel(const float* __restrict__ ws, const float* __restrict__ wd,
                             const float* __restrict__ as_, const float* __restrict__ ad_,
                             float* __restrict__ wp)
{
    int k = blockIdx.x * blockDim.x + threadIdx.x;
    if (k >= 512) return;
#pragma unroll
    for (int h = 0; h < 4; h++) {
        float s1 = 0.f, s2 = 0.f;
        for (int d = 0; d < 128; d++) {
            s1 = fmaf(ws[(size_t)k * 512 + h * 128 + d], as_[h * 128 + d], s1);
            s2 = fmaf(wd[(size_t)k * 512 + h * 128 + d], ad_[h * 128 + d], s2);
        }
        wp[h * 512 + k] = s1;
        wp[(4 + h) * 512 + k] = s2;
    }
}

__global__ void biascat_dec_kernel(const float* __restrict__ a, const float* __restrict__ b,
                                   float* __restrict__ out)
{
    int i = blockIdx.x * blockDim.x + threadIdx.x;
    if (i < 256) out[i] = a[i];
    else if (i < 512) out[i] = b[i - 256];
}

__global__ void __launch_bounds__(256)
coef_kernel(const char* __restrict__ hh, const char* __restrict__ hl,
            const float* __restrict__ wp,
            float* __restrict__ asrc, float* __restrict__ adst)
{
    __shared__ float swp[8 * 512];
    for (int i = threadIdx.x; i < 8 * 512; i += blockDim.x) swp[i] = wp[i];
    __syncthreads();
    int warp = (blockIdx.x * blockDim.x + threadIdx.x) >> 5;
    int lane = threadIdx.x & 31;
    if (warp >= NN) return;
    float acc[8] = {0.f, 0.f, 0.f, 0.f, 0.f, 0.f, 0.f, 0.f};
    const size_t tb = (size_t)(warp >> 7) * 16 * 8192;
    const uint32_t rsw = swz64((uint32_t)((warp & 127) * 64 + lane * 2));
#pragma unroll
    for (int i = 0; i < 16; i++) {
        size_t o = tb + (size_t)i * 8192 + rsw;
        float hv = __bfloat162float(*(const __nv_bfloat16*)(hh + o))
                 + __bfloat162float(*(const __nv_bfloat16*)(hl + o));
        int k = lane + i * 32;
#pragma unroll
        for (int j = 0; j < 8; j++) acc[j] = fmaf(hv, swp[j * 512 + k], acc[j]);
    }
#pragma unroll
    for (int o = 16; o > 0; o >>= 1)
#pragma unroll
        for (int j = 0; j < 8; j++) acc[j] += __shfl_xor_sync(0xffffffffu, acc[j], o);
    if (lane == 0) {
#pragma unroll
        for (int h = 0; h < 4; h++) {
            asrc[warp * 4 + h] = acc[h];
            adst[warp * 4 + h] = acc[4 + h];
        }
    }
}

// ---------------- CSR build ----------------
__global__ void zero_int_kernel(int* p, int n)
{
    int i = blockIdx.x * blockDim.x + threadIdx.x;
    if (i < n) p[i] = 0;
}
__global__ void count_kernel(const int* __restrict__ dst, int* __restrict__ deg, int e)
{
    int i = blockIdx.x * blockDim.x + threadIdx.x;
    if (i < e) atomicAdd(&deg[dst[i]], 1);
}
__global__ void scan_kernel(const int* __restrict__ deg, int* __restrict__ rowptr, int n)
{
    __shared__ int wsum[32];
    __shared__ int carry_s;
    int tid = threadIdx.x, lane = tid & 31, wid = tid >> 5;
    if (tid == 0) carry_s = 0;
    __syncthreads();
    for (int base = 0; base < n; base += 1024) {
        int i = base + tid;
        int v = (i < n) ? deg[i] : 0;
        int s = v;
#pragma unroll
        for (int o = 1; o < 32; o <<= 1) {
            int t = __shfl_up_sync(0xffffffffu, s, o);
            if (lane >= o) s += t;
        }
        if (lane == 31) wsum[wid] = s;
        __syncthreads();
        if (wid == 0) {
            int ws = wsum[lane];
#pragma unroll
            for (int o = 1; o < 32; o <<= 1) {
                int t = __shfl_up_sync(0xffffffffu, ws, o);
                if (lane >= o) ws += t;
            }
            wsum[lane] = ws;
        }
        __syncthreads();
        int pre = (wid > 0) ? wsum[wid - 1] : 0;
        if (i < n) rowptr[i] = carry_s + pre + s - v;
        __syncthreads();
        if (tid == 0) carry_s += wsum[31];
        __syncthreads();
    }
    if (threadIdx.x == 0) rowptr[n] = carry_s;
}
__global__ void scatter_kernel(const int* __restrict__ src, const int* __restrict__ dst,
                               const int* __restrict__ rowptr, int* __restrict__ cursor,
                               int* __restrict__ csr, int e)
{
    int i = blockIdx.x * blockDim.x + threadIdx.x;
    if (i < e) {
        int d = dst[i];
        int pos = rowptr[d] + atomicAdd(&cursor[d], 1);
        csr[pos] = src[i];
    }
}

// ---------------- GAT aggregation (tiled hi/lo output) ----------------
__device__ __forceinline__ float leaky(float v) { return v > 0.f ? v : NEG_SLOPE * v; }

__global__ void __launch_bounds__(256)
agg_kernel(const int* __restrict__ rowptr, const int* __restrict__ csr,
           const float* __restrict__ a_src, const float* __restrict__ a_dst,
           const float* __restrict__ xs, int ldx,
           const float* __restrict__ lin, int ldl,
           char* __restrict__ out_h, char* __restrict__ out_l)
{
    int warp = (blockIdx.x * blockDim.x + threadIdx.x) >> 5;
    int lane = threadIdx.x & 31;
    if (warp >= NN) return;
    const int node = warp;
    const int beg = rowptr[node];
    const int end = rowptr[node + 1];

    const float ad0 = a_dst[node * 4 + 0];
    const float ad1 = a_dst[node * 4 + 1];
    const float ad2 = a_dst[node * 4 + 2];
    const float ad3 = a_dst[node * 4 + 3];

    float m0 = -1e30f, m1 = -1e30f, m2 = -1e30f, m3 = -1e30f;
    for (int i = beg + lane; i < end; i += 32) {
        int s = csr[i];
        const float* ap = a_src + (size_t)s * 4;
        m0 = fmaxf(m0, leaky(ap[0] + ad0));
        m1 = fmaxf(m1, leaky(ap[1] + ad1));
        m2 = fmaxf(m2, leaky(ap[2] + ad2));
        m3 = fmaxf(m3, leaky(ap[3] + ad3));
    }
#pragma unroll
    for (int o = 16; o > 0; o >>= 1) {
        m0 = fmaxf(m0, __shfl_xor_sync(0xffffffffu, m0, o));
        m1 = fmaxf(m1, __shfl_xor_sync(0xffffffffu, m1, o));
        m2 = fmaxf(m2, __shfl_xor_sync(0xffffffffu, m2, o));
        m3 = fmaxf(m3, __shfl_xor_sync(0xffffffffu, m3, o));
    }

    float s0 = 0.f, s1 = 0.f, s2 = 0.f, s3 = 0.f;
    for (int i = beg + lane; i < end; i += 32) {
        int s = csr[i];
        const float* ap = a_src + (size_t)s * 4;
        s0 += expf(leaky(ap[0] + ad0) - m0);
        s1 += expf(leaky(ap[1] + ad1) - m1);
        s2 += expf(leaky(ap[2] + ad2) - m2);
        s3 += expf(leaky(ap[3] + ad3) - m3);
    }
#pragma unroll
    for (int o = 16; o > 0; o >>= 1) {
        s0 += __shfl_xor_sync(0xffffffffu, s0, o);
        s1 += __shfl_xor_sync(0xffffffffu, s1, o);
        s2 += __shfl_xor_sync(0xffffffffu, s2, o);
        s3 += __shfl_xor_sync(0xffffffffu, s3, o);
    }

    const int myh = lane >> 3;
    const float m_my   = (myh < 2) ? (myh == 0 ? m0 : m1) : (myh == 2 ? m2 : m3);
    const float sum_my = (myh < 2) ? (myh == 0 ? s0 : s1) : (myh == 2 ? s2 : s3);
    const float ad_my  = (myh < 2) ? (myh == 0 ? ad0 : ad1) : (myh == 2 ? ad2 : ad3);
    const float inv_my = 1.f / (sum_my + 1e-16f);

    float4 acc0 = make_float4(0.f, 0.f, 0.f, 0.f);
    float4 acc1 = acc0, acc2 = acc0, acc3 = acc0;

    for (int i = beg; i < end; i++) {
        int s = csr[i];
        float v = leaky(a_src[(size_t)s * 4 + myh] + ad_my);
        float w = expf(v - m_my) * inv_my;
        const float4* xp = (const float4*)(xs + (size_t)s * ldx + lane * 16);
        float4 x0 = xp[0], x1 = xp[1], x2 = xp[2], x3 = xp[3];
        acc0.x = fmaf(w, x0.x, acc0.x); acc0.y = fmaf(w, x0.y, acc0.y);
        acc0.z = fmaf(w, x0.z, acc0.z); acc0.w = fmaf(w, x0.w, acc0.w);
        acc1.x = fmaf(w, x1.x, acc1.x); acc1.y = fmaf(w, x1.y, acc1.y);
        acc1.z = fmaf(w, x1.z, acc1.z); acc1.w = fmaf(w, x1.w, acc1.w);
        acc2.x = fmaf(w, x2.x, acc2.x); acc2.y = fmaf(w, x2.y, acc2.y);
        acc2.z = fmaf(w, x2.z, acc2.z); acc2.w = fmaf(w, x2.w, acc2.w);
        acc3.x = fmaf(w, x3.x, acc3.x); acc3.y = fmaf(w, x3.y, acc3.y);
        acc3.z = fmaf(w, x3.z, acc3.z); acc3.w = fmaf(w, x3.w, acc3.w);
    }

    const float4* lp = (const float4*)(lin + (size_t)node * ldl + lane * 16);
    float4 l0 = lp[0], l1 = lp[1], l2 = lp[2], l3 = lp[3];
    float r[16];
    r[0]  = fmaxf(acc0.x + l0.x, 0.f); r[1]  = fmaxf(acc0.y + l0.y, 0.f);
    r[2]  = fmaxf(acc0.z + l0.z, 0.f); r[3]  = fmaxf(acc0.w + l0.w, 0.f);
    r[4]  = fmaxf(acc1.x + l1.x, 0.f); r[5]  = fmaxf(acc1.y + l1.y, 0.f);
    r[6]  = fmaxf(acc1.z + l1.z, 0.f); r[7]  = fmaxf(acc1.w + l1.w, 0.f);
    r[8]  = fmaxf(acc2.x + l2.x, 0.f); r[9]  = fmaxf(acc2.y + l2.y, 0.f);
    r[10] = fmaxf(acc2.z + l2.z, 0.f); r[11] = fmaxf(acc2.w + l2.w, 0.f);
    r[12] = fmaxf(acc3.x + l3.x, 0.f); r[13] = fmaxf(acc3.y + l3.y, 0.f);
    r[14] = fmaxf(acc3.z + l3.z, 0.f); r[15] = fmaxf(acc3.w + l3.w, 0.f);

    uint32_t hw[8], lw[8];
#pragma unroll
    for (int j = 0; j < 8; j++) {
        __nv_bfloat16 h0 = __float2bfloat16(r[2 * j]);
        __nv_bfloat16 h1 = __float2bfloat16(r[2 * j + 1]);
        hw[j] = ((uint32_t)(*(uint16_t*)&h1) << 16) | (*(uint16_t*)&h0);
        lw[j] = pack_bf16x2(r[2 * j]     - __bfloat162float(h0),
                            r[2 * j + 1] - __bfloat162float(h1));
    }
    const size_t tb = ((size_t)(node >> 7) * 16 + (lane >> 1)) * 8192;
    const uint32_t base = (uint32_t)((node & 127) * 64 + (lane & 1) * 32);
    const size_t o0 = tb + swz64(base);
    const size_t o1 = tb + swz64(base + 16);
    *(uint4*)(out_h + o0) = make_uint4(hw[0], hw[1], hw[2], hw[3]);
    *(uint4*)(out_h + o1) = make_uint4(hw[4], hw[5], hw[6], hw[7]);
    *(uint4*)(out_l + o0) = make_uint4(lw[0], lw[1], lw[2], lw[3]);
    *(uint4*)(out_l + o1) = make_uint4(lw[4], lw[5], lw[6], lw[7]);
}

// ---------------- host ----------------
static void tgemm(const void* Ah, const void* Al, int aChTot, int aChOff,
                  const void* Bh, const void* Bl, int bChTot,
                  float* C, int ldc,
                  void* Chi, void* Clo, int oChTot, int oColBase,
                  int M, int N, int Npad, int nchunks,
                  const float* b1, const float* b2, int relu)
{
    dim3 grid(Npad / 128, MTILES);
    tc_gemm<<<grid, GTHREADS, GEMM_SMEM>>>(
        (const char*)Ah, (const char*)Al, aChTot, aChOff,
        (const char*)Bh, (const char*)Bl, bChTot, C, ldc,
        (char*)Chi, (char*)Clo, oChTot, oColBase,
        M, N, nchunks, b1, b2, relu);
}

template <typename T>
static T* sym(T* s) { void* p = nullptr; cudaGetSymbolAddress(&p, (const void*)s); return (T*)p; }

extern "C" void kernel_launch(void* const* d_in, const int* in_sizes, int n_in,
                              void* d_out, int out_size)
{
    const float* x      = (const float*)d_in[0];
    const int*   ei     = (const int*)d_in[1];
    const float* W_rna  = (const float*)d_in[2];
    const float* b_rna  = (const float*)d_in[3];
    const float* W_prot = (const float*)d_in[4];
    const float* b_prot = (const float*)d_in[5];
    const float* g1_ws  = (const float*)d_in[6];
    const float* g1_wd  = (const float*)d_in[7];
    const float* g1_as  = (const float*)d_in[8];
    const float* g1_ad  = (const float*)d_in[9];
    const float* g1_b   = (const float*)d_in[10];
    const float* l1_w   = (const float*)d_in[11];
    const float* l1_b   = (const float*)d_in[12];
    const float* g2_ws  = (const float*)d_in[13];
    const float* g2_wd  = (const float*)d_in[14];
    const float* g2_as  = (const float*)d_in[15];
    const float* g2_ad  = (const float*)d_in[16];
    const float* g2_b   = (const float*)d_in[17];
    const float* l2_w   = (const float*)d_in[18];
    const float* l2_b   = (const float*)d_in[19];
    const float* agg_w  = (const float*)d_in[20];
    const float* agg_b  = (const float*)d_in[21];
    const float* dr_w   = (const float*)d_in[22];
    const float* dr_b   = (const float*)d_in[23];
    const float* dp_w   = (const float*)d_in[24];
    const float* dp_b   = (const float*)d_in[25];
    const float* rr_w   = (const float*)d_in[26];
    const float* rr_b   = (const float*)d_in[27];
    const float* rp_w   = (const float*)d_in[28];
    const float* rp_b   = (const float*)d_in[29];

    float* out = (float*)d_out;
    float* out_rna  = out;
    float* out_prot = out + (size_t)NN * RNA;
    float* out_emb  = out + (size_t)NN * (RNA + PROT);

    cudaFuncSetAttribute(tc_gemm, cudaFuncAttributeMaxDynamicSharedMemorySize, GEMM_SMEM);

    __nv_bfloat16 *xr_h = sym(g_xr_h), *xr_l = sym(g_xr_l);
    __nv_bfloat16 *xp_h = sym(g_xp_h), *xp_l = sym(g_xp_l);
    __nv_bfloat16 *hh = sym(g_hh), *hl = sym(g_hl);
    __nv_bfloat16 *eh = sym(g_eh), *el = sym(g_el);
    __nv_bfloat16 *rdh = sym(g_rdh), *rdl = sym(g_rdl);
    float *xslin = sym(g_xslin);
    float *asrc = sym(g_asrc), *adst = sym(g_adst);
    float *wp1 = sym(g_wp1), *wp2 = sym(g_wp2);
    float *bcat1 = sym(g_bcat1), *bcat2 = sym(g_bcat2), *bcatd = sym(g_bcatd);
    int *deg = sym(g_deg), *cur = sym(g_cursor), *rowptr = sym(g_rowptr), *csr = sym(g_csr);

    __nv_bfloat16 *wr_h = sym(g_wr_h), *wr_l = sym(g_wr_l);
    __nv_bfloat16 *wp_h = sym(g_wp_h), *wp_l = sym(g_wp_l);
    __nv_bfloat16 *wc1_h = sym(g_wc1_h), *wc1_l = sym(g_wc1_l);
    __nv_bfloat16 *wc2_h = sym(g_wc2_h), *wc2_l = sym(g_wc2_l);
    __nv_bfloat16 *wagg_h = sym(g_wagg_h), *wagg_l = sym(g_wagg_l);
    __nv_bfloat16 *wdc_h = sym(g_wdc_h), *wdc_l = sym(g_wdc_l);
    __nv_bfloat16 *wrr_h = sym(g_wrr_h), *wrr_l = sym(g_wrr_l);
    __nv_bfloat16 *wrp_h = sym(g_wrp_h), *wrp_l = sym(g_wrp_l);

    const int* e_src = ei;
    const int* e_dst = ei + EE;

    #define TSPLIT(W, K, N_, Kp, Np, H, L) \
        tsplit_kernel<<<(unsigned)(((long)(Np) * (Kp) + 255) / 256), 256>>>( \
            W, K, N_, Kp, Np, (char*)(H), (char*)(L))

    const int nAgg = (NN * 32 + 255) / 256;

    // weight prep
    TSPLIT(W_rna,  RNA,  EMB, 2048, 256, wr_h,  wr_l);
    TSPLIT(W_prot, PROT, EMB, 128,  256, wp_h,  wp_l);
    prep_layer_kernel<<<2052, 256>>>(g1_ws, l1_w, l1_b, g1_b,
                                     (char*)wc1_h, (char*)wc1_l, bcat1);

    // x split -> tiled hi/lo (once), then bulk embed GEMMs
    {
        long t1 = (long)MPAD * 64 * 8;
        splitx_kernel<<<(unsigned)((t1 + 255) / 256), 256>>>(
            x, INF, 0, NN, RNA, 64, (char*)xr_h, (char*)xr_l);
        long t2 = (long)MPAD * 4 * 8;
        splitx_kernel<<<(unsigned)((t2 + 255) / 256), 256>>>(
            x, INF, RNA, NN, PROT, 4, (char*)xp_h, (char*)xp_l);
    }
    tgemm(xr_h, xr_l, 64, 0, wr_h, wr_l, 64, nullptr, 0,
          hh, hl, 16, 0, NN, 256, 256, 63, b_rna, nullptr, 0);
    tgemm(xp_h, xp_l, 4, 0, wp_h, wp_l, 4, nullptr, 0,
          hh, hl, 16, 256, NN, 256, 256, 4, b_prot, nullptr, 0);

    // GAT layer 1 fused [xs|lin] GEMM (bulk)
    tgemm(hh, hl, 16, 0, wc1_h, wc1_l, 16, xslin, 1024,
          nullptr, nullptr, 0, 0, NN, 1024, 1024, 16, bcat1, nullptr, 0);
    wproj_kernel<<<2, 256>>>(g1_ws, g1_wd, g1_as, g1_ad, wp1);
    coef_kernel<<<nAgg, 256>>>((const char*)hh, (const char*)hl, wp1, asrc, adst);
    zero_int_kernel<<<(NN + 255) / 256, 256>>>(deg, NN);
    zero_int_kernel<<<(NN + 255) / 256, 256>>>(cur, NN);
    count_kernel<<<(EE + 255) / 256, 256>>>(e_dst, deg, EE);
    scan_kernel<<<1, 1024>>>(deg, rowptr, NN);
    scatter_kernel<<<(EE + 255) / 256, 256>>>(e_src, e_dst, rowptr, cur, csr, EE);
    agg_kernel<<<nAgg, 256>>>(rowptr, csr, asrc, adst,
                              xslin, 1024, xslin + 512, 1024,
                              (char*)hh, (char*)hl);

    // GAT layer 2
    prep_layer_kernel<<<2052, 256>>>(g2_ws, l2_w, l2_b, g2_b,
                                     (char*)wc2_h, (char*)wc2_l, bcat2);
    tgemm(hh, hl, 16, 0, wc2_h, wc2_l, 16, xslin, 1024,
          nullptr, nullptr, 0, 0, NN, 1024, 1024, 16, bcat2, nullptr, 0);
    wproj_kernel<<<2, 256>>>(g2_ws, g2_wd, g2_as, g2_ad, wp2);
    coef_kernel<<<nAgg, 256>>>((const char*)hh, (const char*)hl, wp2, asrc, adst);
    agg_kernel<<<nAgg, 256>>>(rowptr, csr, asrc, adst,
                              xslin, 1024, xslin + 512, 1024,
                              (char*)hh, (char*)hl);

    // head: embedding
    TSPLIT(agg_w, HD, HID, 512, 128, wagg_h, wagg_l);
    tgemm(hh, hl, 16, 0, wagg_h, wagg_l, 16, out_emb, HID,
          eh, el, 4, 0, NN, HID, 128, 16, agg_b, nullptr, 1);

    // decoders (fused)
    TSPLIT(dr_w, HID, EMB, 128, 256, wdc_h,             wdc_l);
    TSPLIT(dp_w, HID, EMB, 128, 256, (char*)wdc_h + 65536, (char*)wdc_l + 65536);
    biascat_dec_kernel<<<2, 256>>>(dr_b, dp_b, bcatd);
    tgemm(eh, el, 4, 0, wdc_h, wdc_l, 4, nullptr, 0,
          rdh, rdl, 16, 0, NN, 512, 512, 4, bcatd, nullptr, 0);

    // reconstructions
    TSPLIT(rr_w, EMB, RNA, 256, 2048, wrr_h, wrr_l);
    tgemm(rdh, rdl, 16, 0, wrr_h, wrr_l, 8, out_rna, RNA,
          nullptr, nullptr, 0, 0, NN, RNA, 2048, 8, rr_b, nullptr, 0);
    TSPLIT(rp_w, EMB, PROT, 256, 128, wrp_h, wrp_l);
    tgemm(rdh, rdl, 16, 8, wrp_h, wrp_l, 8, out_prot, PROT,
          nullptr, nullptr, 0, 0, NN, PROT, 128, 8, rp_b, nullptr, 0);
}

// round 16
// speedup vs baseline: 1.0376x; 1.0376x over previous
#include <cuda_runtime.h>
#include <cuda_bf16.h>
#include <math.h>
#include <stdint.h>

#define NN     20000
#define EE     320000
#define RNA    2000
#define PROT   100
#define EMB    256
#define HID    128
#define NHEAD  4
#define HD     512
#define INF    2100
#define NEG_SLOPE 0.2f

#define MPAD   20096
#define MTILES 157

#define KCH         32
#define STAGES      3
#define STAGE_BYTES 32768                        // Ah,Al,Bh,Bl x 8KB
#define GEMM_SMEM   (STAGES * STAGE_BYTES + 128) // + full/empty mbarriers
#define GTHREADS    512

// ---------------- device scratch (zero-init at load) ----------------
// bf16 hi/lo buffers use TILED layout:
//   [row_tile][k_chunk][8192B swizzled block]  (block = 128 rows x 32 cols SW64)
__device__ __align__(16) __nv_bfloat16 g_xr_h[(size_t)MPAD * 2048];
__device__ __align__(16) __nv_bfloat16 g_xr_l[(size_t)MPAD * 2048];
__device__ __align__(16) __nv_bfloat16 g_xp_h[(size_t)MPAD * 128];
__device__ __align__(16) __nv_bfloat16 g_xp_l[(size_t)MPAD * 128];
__device__ __align__(16) __nv_bfloat16 g_hh[(size_t)MPAD * 512];
__device__ __align__(16) __nv_bfloat16 g_hl[(size_t)MPAD * 512];
__device__ __align__(16) __nv_bfloat16 g_eh[(size_t)MPAD * 128];
__device__ __align__(16) __nv_bfloat16 g_el[(size_t)MPAD * 128];
__device__ __align__(16) __nv_bfloat16 g_rdh[(size_t)MPAD * 512];
__device__ __align__(16) __nv_bfloat16 g_rdl[(size_t)MPAD * 512];

__device__ __align__(16) float g_xslin[(size_t)MPAD * 1024];
__device__ __align__(16) float g_asrc[(size_t)NN * NHEAD];
__device__ __align__(16) float g_adst[(size_t)NN * NHEAD];
__device__ __align__(16) float g_wp1[8 * 512];
__device__ __align__(16) float g_wp2[8 * 512];
__device__ __align__(16) float g_bcat1[1024];
__device__ __align__(16) float g_bcat2[1024];
__device__ __align__(16) float g_bcatd[512];

__device__ __align__(16) __nv_bfloat16 g_wr_h[256 * 2048],   g_wr_l[256 * 2048];
__device__ __align__(16) __nv_bfloat16 g_wp_h[256 * 128],    g_wp_l[256 * 128];
__device__ __align__(16) __nv_bfloat16 g_wc1_h[1024 * 512],  g_wc1_l[1024 * 512];
__device__ __align__(16) __nv_bfloat16 g_wc2_h[1024 * 512],  g_wc2_l[1024 * 512];
__device__ __align__(16) __nv_bfloat16 g_wagg_h[128 * 512],  g_wagg_l[128 * 512];
__device__ __align__(16) __nv_bfloat16 g_wdc_h[512 * 128],   g_wdc_l[512 * 128];
__device__ __align__(16) __nv_bfloat16 g_wrr_h[2048 * 256],  g_wrr_l[2048 * 256];
__device__ __align__(16) __nv_bfloat16 g_wrp_h[128 * 256],   g_wrp_l[128 * 256];

__device__ int g_deg[NN];
__device__ int g_cursor[NN];
__device__ int g_rowptr[NN + 1];
__device__ int g_csr[EE];

// ---------------- PTX helpers ----------------
__device__ __forceinline__ uint32_t smem_u32(const void* p) {
    uint32_t a;
    asm("{ .reg .u64 t; cvta.to.shared.u64 t, %1; cvt.u32.u64 %0, t; }" : "=r"(a) : "l"(p));
    return a;
}
__device__ __forceinline__ void bulk8k(uint32_t dst, const void* src, uint32_t mbar) {
    asm volatile(
        "cp.async.bulk.shared::cta.global.mbarrier::complete_tx::bytes [%0], [%1], %2, [%3];"
        :: "r"(dst), "l"(src), "r"(8192), "r"(mbar) : "memory");
}
#define MBAR_INIT(a, c) \
    asm volatile("mbarrier.init.shared.b64 [%0], %1;" :: "r"(a), "r"(c) : "memory")
#define MBAR_EXPECT(a, tx) \
    asm volatile("mbarrier.arrive.expect_tx.shared.b64 _, [%0], %1;" :: "r"(a), "r"(tx) : "memory")
#define MBAR_ARRIVE(a) \
    asm volatile("mbarrier.arrive.shared.b64 _, [%0];" :: "r"(a) : "memory")
__device__ __forceinline__ void mbar_wait(uint32_t a, int par) {
    asm volatile(
        "{\n\t.reg .pred P;\n\t"
        "W_%=:\n\t"
        "mbarrier.try_wait.parity.acquire.cta.shared::cta.b64 P, [%0], %1, 0x989680;\n\t"
        "@P bra.uni D_%=;\n\t"
        "bra.uni W_%=;\n\t"
        "D_%=:\n\t}"
        :: "r"(a), "r"(par) : "memory");
}

__device__ __forceinline__ uint32_t swz64(uint32_t off) {
    return off ^ ((off >> 3) & 0x30);
}
__device__ __forceinline__ size_t toff(int row, int k, int chTot) {
    return ((size_t)((row >> 7) * chTot + (k >> 5))) * 8192
         + swz64((uint32_t)((row & 127) * 64 + (k & 31) * 2));
}
__device__ __forceinline__ void ldm_x4(uint32_t addr, uint32_t r[4]) {
    asm volatile("ldmatrix.sync.aligned.m8n8.x4.shared.b16 {%0,%1,%2,%3}, [%4];"
                 : "=r"(r[0]), "=r"(r[1]), "=r"(r[2]), "=r"(r[3]) : "r"(addr));
}
__device__ __forceinline__ void mma_bf16(float c[4], const uint32_t a[4],
                                         uint32_t b0, uint32_t b1) {
    asm volatile(
        "mma.sync.aligned.m16n8k16.row.col.f32.bf16.bf16.f32 "
        "{%0,%1,%2,%3}, {%4,%5,%6,%7}, {%8,%9}, {%0,%1,%2,%3};"
        : "+f"(c[0]), "+f"(c[1]), "+f"(c[2]), "+f"(c[3])
        : "r"(a[0]), "r"(a[1]), "r"(a[2]), "r"(a[3]), "r"(b0), "r"(b1));
}
__device__ __forceinline__ uint32_t pack_bf16x2(float a, float b) {
    __nv_bfloat162 t = __floats2bfloat162_rn(a, b);
    return *(uint32_t*)&t;
}

// ---------------- warp-MMA GEMM (bulk, decoupled warps) ----------------
// Round-13 certified inner loop: B-first, Ah reloaded (20 LDSM / 48 MMA per
// warp per chunk). Per stage: full mbarrier (tx, count 1) + empty (count 16).
__global__ void __launch_bounds__(GTHREADS, 2)
tc_gemm(const char* __restrict__ Ah, const char* __restrict__ Al, int aChTot, int aChOff,
        const char* __restrict__ Bh, const char* __restrict__ Bl, int bChTot,
        float* __restrict__ C, int ldc,
        char* __restrict__ Chi, char* __restrict__ Clo, int oChTot, int oColBase,
        int M, int N, int nchunks,
        const float* __restrict__ bias1, const float* __restrict__ bias2, int relu)
{
    extern __shared__ char smem[];
    const uint32_t sm = smem_u32(smem);
    const uint32_t mbF = sm + STAGES * STAGE_BYTES;        // full[0..2]
    const uint32_t mbE = mbF + 8 * STAGES;                 // empty[0..2]
    const int tid = threadIdx.x;
    const int wid = tid >> 5, lane = tid & 31;
    const int row0 = blockIdx.y * 128;
    const int col0 = blockIdx.x * 128;

    const int wm = wid & 3;
    const int wn = wid >> 2;
    const int li    = lane & 7;
    const int matm  = (lane >> 3) & 1;
    const int khalf = lane >> 4;

    const size_t aBase = (size_t)(blockIdx.y * aChTot + aChOff) * 8192;
    const size_t bBase = (size_t)(blockIdx.x * bChTot) * 8192;

    float acc[2][4][4];
#pragma unroll
    for (int a = 0; a < 2; a++)
#pragma unroll
        for (int b = 0; b < 4; b++)
#pragma unroll
            for (int c = 0; c < 4; c++) acc[a][b][c] = 0.f;

    if (tid == 0) {
#pragma unroll
        for (int s = 0; s < STAGES; s++) {
            MBAR_INIT(mbF + 8 * s, 1);
            MBAR_INIT(mbE + 8 * s, 16);
        }
    }
    __syncthreads();

#define LOADC(cc) do { \
    const int s_ = (cc) % STAGES; \
    const uint32_t st_ = sm + (uint32_t)s_ * STAGE_BYTES; \
    const uint32_t mb_ = mbF + 8 * s_; \
    MBAR_EXPECT(mb_, STAGE_BYTES); \
    bulk8k(st_,         Ah + aBase + (size_t)(cc) * 8192, mb_); \
    bulk8k(st_ + 8192,  Al + aBase + (size_t)(cc) * 8192, mb_); \
    bulk8k(st_ + 16384, Bh + bBase + (size_t)(cc) * 8192, mb_); \
    bulk8k(st_ + 24576, Bl + bBase + (size_t)(cc) * 8192, mb_); \
} while (0)

    if (tid == 0) {
        for (int c = 0; c < 2 && c < nchunks; c++) LOADC(c);
    }

    for (int c = 0; c < nchunks; c++) {
        const int s = c % STAGES;
        const uint32_t sb = sm + (uint32_t)s * STAGE_BYTES;

        if (tid == 0 && c + 2 < nchunks) {
            if (c >= 1) mbar_wait(mbE + 8 * ((c + 2) % STAGES), ((c - 1) / STAGES) & 1);
            LOADC(c + 2);
        }
        mbar_wait(mbF + 8 * s, (c / STAGES) & 1);

#pragma unroll
        for (int ks = 0; ks < 2; ks++) {
            const int kb = ks * 32 + khalf * 16;
            uint32_t b[2][4];
            uint32_t aoff[2], boff[2];
#pragma unroll
            for (int mi = 0; mi < 2; mi++)
                aoff[mi] = swz64((uint32_t)((wm * 32 + mi * 16 + matm * 8 + li) * 64 + kb));
#pragma unroll
            for (int nj = 0; nj < 2; nj++)
                boff[nj] = swz64((uint32_t)((wn * 32 + nj * 16 + matm * 8 + li) * 64 + kb));

#pragma unroll
            for (int nj = 0; nj < 2; nj++) ldm_x4(sb + 16384 + boff[nj], b[nj]);
#pragma unroll
            for (int mi = 0; mi < 2; mi++) {
                uint32_t a[4];
                ldm_x4(sb + aoff[mi], a);           // Ah
#pragma unroll
                for (int ni = 0; ni < 4; ni++) {
                    const int nj = ni >> 1, s2 = ni & 1;
                    mma_bf16(acc[mi][ni], a, b[nj][s2], b[nj][s2 + 2]);
                }
                ldm_x4(sb + 8192 + aoff[mi], a);    // Al
#pragma unroll
                for (int ni = 0; ni < 4; ni++) {
                    const int nj = ni >> 1, s2 = ni & 1;
                    mma_bf16(acc[mi][ni], a, b[nj][s2], b[nj][s2 + 2]);
                }
            }
#pragma unroll
            for (int nj = 0; nj < 2; nj++) ldm_x4(sb + 24576 + boff[nj], b[nj]);
#pragma unroll
            for (int mi = 0; mi < 2; mi++) {
                uint32_t a[4];
                ldm_x4(sb + aoff[mi], a);           // Ah * Bl
#pragma unroll
                for (int ni = 0; ni < 4; ni++) {
                    const int nj = ni >> 1, s2 = ni & 1;
                    mma_bf16(acc[mi][ni], a, b[nj][s2], b[nj][s2 + 2]);
                }
            }
        }
        if (lane == 0) MBAR_ARRIVE(mbE + 8 * s);
    }
#undef LOADC

    // epilogue: acc -> smem fp32 (stride 132) -> coalesced global
    __syncthreads();
    float* eps = (float*)smem;
    const int grp = lane >> 2, qp = lane & 3;
#pragma unroll
    for (int mi = 0; mi < 2; mi++) {
#pragma unroll
        for (int ni = 0; ni < 4; ni++) {
            const int r = wm * 32 + mi * 16 + grp;
            const int col = wn * 32 + ni * 8 + qp * 2;
            eps[r * 132 + col]           = acc[mi][ni][0];
            eps[r * 132 + col + 1]       = acc[mi][ni][1];
            eps[(r + 8) * 132 + col]     = acc[mi][ni][2];
            eps[(r + 8) * 132 + col + 1] = acc[mi][ni][3];
        }
    }
    __syncthreads();

#pragma unroll
    for (int i = 0; i < 8; i++) {
        const int f = tid + i * GTHREADS;
        const int r = f >> 5, c4 = f & 31;
        const int grow = row0 + r;
        const int col = col0 + c4 * 4;
        if (grow >= M || col >= N) continue;
        float v[4];
#pragma unroll
        for (int j = 0; j < 4; j++) {
            v[j] = eps[r * 132 + c4 * 4 + j];
            const int cc = col + j;
            if (cc < N) {
                if (bias1) v[j] += bias1[cc];
                if (bias2) v[j] += bias2[cc];
                if (relu)  v[j] = fmaxf(v[j], 0.f);
            }
        }
        if (C) {
            if (col + 3 < N) {
                *(float4*)(C + (size_t)grow * ldc + col) = make_float4(v[0], v[1], v[2], v[3]);
            } else {
#pragma unroll
                for (int j = 0; j < 4; j++)
                    if (col + j < N) C[(size_t)grow * ldc + col + j] = v[j];
            }
        }
        if (Chi) {
            __nv_bfloat16 h[4];
            float lo[4];
#pragma unroll
            for (int j = 0; j < 4; j++) {
                h[j] = __float2bfloat16(v[j]);
                lo[j] = v[j] - __bfloat162float(h[j]);
            }
            uint32_t h01 = ((uint32_t)(*(uint16_t*)&h[1]) << 16) | (*(uint16_t*)&h[0]);
            uint32_t h23 = ((uint32_t)(*(uint16_t*)&h[3]) << 16) | (*(uint16_t*)&h[2]);
            uint32_t l01 = pack_bf16x2(lo[0], lo[1]);
            uint32_t l23 = pack_bf16x2(lo[2], lo[3]);
            size_t o = toff(grow, oColBase + col, oChTot);
            *(uint2*)(Chi + o) = make_uint2(h01, h23);
            *(uint2*)(Clo + o) = make_uint2(l01, l23);
        }
    }
}

// ---------------- conversions / small kernels ----------------
__global__ void splitx_kernel(const float* __restrict__ x, int lda, int colOff,
                              int M, int K, int chTot,
                              char* __restrict__ h, char* __restrict__ l)
{
    const int qpr = chTot * 8;
    long idx = (long)blockIdx.x * blockDim.x + threadIdx.x;
    long total = (long)MPAD * qpr;
    if (idx >= total) return;
    int row = (int)(idx / qpr);
    int k = (int)(idx % qpr) * 4;
    float f[4];
#pragma unroll
    for (int j = 0; j < 4; j++) {
        int kk = k + j;
        f[j] = (row < M && kk < K) ? x[(size_t)row * lda + colOff + kk] : 0.f;
    }
    __nv_bfloat16 h0 = __float2bfloat16(f[0]);
    __nv_bfloat16 h1 = __float2bfloat16(f[1]);
    __nv_bfloat16 h2 = __float2bfloat16(f[2]);
    __nv_bfloat16 h3 = __float2bfloat16(f[3]);
    uint32_t hi01 = ((uint32_t)(*(uint16_t*)&h1) << 16) | (*(uint16_t*)&h0);
    uint32_t hi23 = ((uint32_t)(*(uint16_t*)&h3) << 16) | (*(uint16_t*)&h2);
    uint32_t lo01 = pack_bf16x2(f[0] - __bfloat162float(h0), f[1] - __bfloat162float(h1));
    uint32_t lo23 = pack_bf16x2(f[2] - __bfloat162float(h2), f[3] - __bfloat162float(h3));
    size_t o = toff(row, k, chTot);
    *(uint2*)(h + o) = make_uint2(hi01, hi23);
    *(uint2*)(l + o) = make_uint2(lo01, lo23);
}

__global__ void tsplit_kernel(const float* __restrict__ W, int K, int N,
                              int Kpad, int Npad,
                              char* __restrict__ h, char* __restrict__ l)
{
    long idx = (long)blockIdx.x * blockDim.x + threadIdx.x;
    long total = (long)Npad * Kpad;
    if (idx >= total) return;
    int n = (int)(idx / Kpad);
    int k = (int)(idx % Kpad);
    float v = 0.f;
    if (n < N && k < K) v = W[(size_t)k * N + n];
    __nv_bfloat16 hi = __float2bfloat16(v);
    __nv_bfloat16 lo = __float2bfloat16(v - __bfloat162float(hi));
    size_t o = toff(n, k, Kpad / 32);
    *(__nv_bfloat16*)(h + o) = hi;
    *(__nv_bfloat16*)(l + o) = lo;
}

// tsplit for dp_w + decoder bias concat fused (one launch)
__global__ void tsplit_dec_kernel(const float* __restrict__ W, int K, int N,
                                  int Kpad, int Npad,
                                  char* __restrict__ h, char* __restrict__ l,
                                  const float* __restrict__ ba, const float* __restrict__ bb,
                                  float* __restrict__ bias)
{
    long idx = (long)blockIdx.x * blockDim.x + threadIdx.x;
    long total = (long)Npad * Kpad;
    if (idx < total) {
        int n = (int)(idx / Kpad);
        int k = (int)(idx % Kpad);
        float v = 0.f;
        if (n < N && k < K) v = W[(size_t)k * N + n];
        __nv_bfloat16 hi = __float2bfloat16(v);
        __nv_bfloat16 lo = __float2bfloat16(v - __bfloat162float(hi));
        size_t o = toff(n, k, Kpad / 32);
        *(__nv_bfloat16*)(h + o) = hi;
        *(__nv_bfloat16*)(l + o) = lo;
    } else {
        long j = idx - total;
        if (j < 256) bias[j] = ba[j];
        else if (j < 512) bias[j] = bb[j - 256];
    }
}

__global__ void prep_layer_kernel(const float* __restrict__ ws, const float* __restrict__ lw,
                                  const float* __restrict__ lb, const float* __restrict__ gb,
                                  char* __restrict__ h, char* __restrict__ l,
                                  float* __restrict__ bias)
{
    long idx = (long)blockIdx.x * blockDim.x + threadIdx.x;
    const long total = 1024L * 512;
    if (idx < total) {
        int n = (int)(idx / 512);
        int k = (int)(idx % 512);
        float v = (n < 512) ? ws[(size_t)k * 512 + n] : lw[(size_t)k * 512 + (n - 512)];
        __nv_bfloat16 hi = __float2bfloat16(v);
        __nv_bfloat16 lo = __float2bfloat16(v - __bfloat162float(hi));
        size_t o = toff(n, k, 16);
        *(__nv_bfloat16*)(h + o) = hi;
        *(__nv_bfloat16*)(l + o) = lo;
    } else {
        long j = idx - total;
        if (j < 512) bias[j] = 0.f;
        else if (j < 1024) bias[j] = lb[j - 512] + gb[j - 512];
    }
}

__global__ void wproj_kernel(const float* __restrict__ ws, const float* __restrict__ wd,
                             const float* __restrict__ as_, const float* __restrict__ ad_,
                             float* __restrict__ wp)
{
    int k = blockIdx.x * blockDim.x + threadIdx.x;
    if (k >= 512) return;
#pragma unroll
    for (int h = 0; h < 4; h++) {
        float s1 = 0.f, s2 = 0.f;
        for (int d = 0; d < 128; d++) {
            s1 = fmaf(ws[(size_t)k * 512 + h * 128 + d], as_[h * 128 + d], s1);
            s2 = fmaf(wd[(size_t)k * 512 + h * 128 + d], ad_[h * 128 + d], s2);
        }
        wp[h * 512 + k] = s1;
        wp[(4 + h) * 512 + k] = s2;
    }
}

__global__ void __launch_bounds__(256)
coef_kernel(const char* __restrict__ hh, const char* __restrict__ hl,
            const float* __restrict__ wp,
            float* __restrict__ asrc, float* __restrict__ adst)
{
    __shared__ float swp[8 * 512];
    for (int i = threadIdx.x; i < 8 * 512; i += blockDim.x) swp[i] = wp[i];
    __syncthreads();
    int warp = (blockIdx.x * blockDim.x + threadIdx.x) >> 5;
    int lane = threadIdx.x & 31;
    if (warp >= NN) return;
    float acc[8] = {0.f, 0.f, 0.f, 0.f, 0.f, 0.f, 0.f, 0.f};
    const size_t tb = (size_t)(warp >> 7) * 16 * 8192;
    const uint32_t rsw = swz64((uint32_t)((warp & 127) * 64 + lane * 2));
#pragma unroll
    for (int i = 0; i < 16; i++) {
        size_t o = tb + (size_t)i * 8192 + rsw;
        float hv = __bfloat162float(*(const __nv_bfloat16*)(hh + o))
                 + __bfloat162float(*(const __nv_bfloat16*)(hl + o));
        int k = lane + i * 32;
#pragma unroll
        for (int j = 0; j < 8; j++) acc[j] = fmaf(hv, swp[j * 512 + k], acc[j]);
    }
#pragma unroll
    for (int o = 16; o > 0; o >>= 1)
#pragma unroll
        for (int j = 0; j < 8; j++) acc[j] += __shfl_xor_sync(0xffffffffu, acc[j], o);
    if (lane == 0) {
#pragma unroll
        for (int h = 0; h < 4; h++) {
            asrc[warp * 4 + h] = acc[h];
            adst[warp * 4 + h] = acc[4 + h];
        }
    }
}

// ---------------- CSR build ----------------
__global__ void zero2_kernel(int* a, int* b, int n)
{
    int i = blockIdx.x * blockDim.x + threadIdx.x;
    if (i < n) { a[i] = 0; b[i] = 0; }
}
__global__ void count_kernel(const int* __restrict__ dst, int* __restrict__ deg, int e)
{
    int i = blockIdx.x * blockDim.x + threadIdx.x;
    if (i < e) atomicAdd(&deg[dst[i]], 1);
}
__global__ void scan_kernel(const int* __restrict__ deg, int* __restrict__ rowptr, int n)
{
    __shared__ int wsum[32];
    __shared__ int carry_s;
    int tid = threadIdx.x, lane = tid & 31, wid = tid >> 5;
    if (tid == 0) carry_s = 0;
    __syncthreads();
    for (int base = 0; base < n; base += 1024) {
        int i = base + tid;
        int v = (i < n) ? deg[i] : 0;
        int s = v;
#pragma unroll
        for (int o = 1; o < 32; o <<= 1) {
            int t = __shfl_up_sync(0xffffffffu, s, o);
            if (lane >= o) s += t;
        }
        if (lane == 31) wsum[wid] = s;
        __syncthreads();
        if (wid == 0) {
            int ws = wsum[lane];
#pragma unroll
            for (int o = 1; o < 32; o <<= 1) {
                int t = __shfl_up_sync(0xffffffffu, ws, o);
                if (lane >= o) ws += t;
            }
            wsum[lane] = ws;
        }
        __syncthreads();
        int pre = (wid > 0) ? wsum[wid - 1] : 0;
        if (i < n) rowptr[i] = carry_s + pre + s - v;
        __syncthreads();
        if (tid == 0) carry_s += wsum[31];
        __syncthreads();
    }
    if (threadIdx.x == 0) rowptr[n] = carry_s;
}
__global__ void scatter_kernel(const int* __restrict__ src, const int* __restrict__ dst,
                               const int* __restrict__ rowptr, int* __restrict__ cursor,
                               int* __restrict__ csr, int e)
{
    int i = blockIdx.x * blockDim.x + threadIdx.x;
    if (i < e) {
        int d = dst[i];
        int pos = rowptr[d] + atomicAdd(&cursor[d], 1);
        csr[pos] = src[i];
    }
}

// ---------------- GAT aggregation (tiled hi/lo output) ----------------
__device__ __forceinline__ float leaky(float v) { return v > 0.f ? v : NEG_SLOPE * v; }

__global__ void __launch_bounds__(256)
agg_kernel(const int* __restrict__ rowptr, const int* __restrict__ csr,
           const float* __restrict__ a_src, const float* __restrict__ a_dst,
           const float* __restrict__ xs, int ldx,
           const float* __restrict__ lin, int ldl,
           char* __restrict__ out_h, char* __restrict__ out_l)
{
    int warp = (blockIdx.x * blockDim.x + threadIdx.x) >> 5;
    int lane = threadIdx.x & 31;
    if (warp >= NN) return;
    const int node = warp;
    const int beg = rowptr[node];
    const int end = rowptr[node + 1];

    const float ad0 = a_dst[node * 4 + 0];
    const float ad1 = a_dst[node * 4 + 1];
    const float ad2 = a_dst[node * 4 + 2];
    const float ad3 = a_dst[node * 4 + 3];

    float m0 = -1e30f, m1 = -1e30f, m2 = -1e30f, m3 = -1e30f;
    for (int i = beg + lane; i < end; i += 32) {
        int s = csr[i];
        const float* ap = a_src + (size_t)s * 4;
        m0 = fmaxf(m0, leaky(ap[0] + ad0));
        m1 = fmaxf(m1, leaky(ap[1] + ad1));
        m2 = fmaxf(m2, leaky(ap[2] + ad2));
        m3 = fmaxf(m3, leaky(ap[3] + ad3));
    }
#pragma unroll
    for (int o = 16; o > 0; o >>= 1) {
        m0 = fmaxf(m0, __shfl_xor_sync(0xffffffffu, m0, o));
        m1 = fmaxf(m1, __shfl_xor_sync(0xffffffffu, m1, o));
        m2 = fmaxf(m2, __shfl_xor_sync(0xffffffffu, m2, o));
        m3 = fmaxf(m3, __shfl_xor_sync(0xffffffffu, m3, o));
    }

    float s0 = 0.f, s1 = 0.f, s2 = 0.f, s3 = 0.f;
    for (int i = beg + lane; i < end; i += 32) {
        int s = csr[i];
        const float* ap = a_src + (size_t)s * 4;
        s0 += expf(leaky(ap[0] + ad0) - m0);
        s1 += expf(leaky(ap[1] + ad1) - m1);
        s2 += expf(leaky(ap[2] + ad2) - m2);
        s3 += expf(leaky(ap[3] + ad3) - m3);
    }
#pragma unroll
    for (int o = 16; o > 0; o >>= 1) {
        s0 += __shfl_xor_sync(0xffffffffu, s0, o);
        s1 += __shfl_xor_sync(0xffffffffu, s1, o);
        s2 += __shfl_xor_sync(0xffffffffu, s2, o);
        s3 += __shfl_xor_sync(0xffffffffu, s3, o);
    }

    const int myh = lane >> 3;
    const float m_my   = (myh < 2) ? (myh == 0 ? m0 : m1) : (myh == 2 ? m2 : m3);
    const float sum_my = (myh < 2) ? (myh == 0 ? s0 : s1) : (myh == 2 ? s2 : s3);
    const float ad_my  = (myh < 2) ? (myh == 0 ? ad0 : ad1) : (myh == 2 ? ad2 : ad3);
    const float inv_my = 1.f / (sum_my + 1e-16f);

    float4 acc0 = make_float4(0.f, 0.f, 0.f, 0.f);
    float4 acc1 = acc0, acc2 = acc0, acc3 = acc0;

    for (int i = beg; i < end; i++) {
        int s = csr[i];
        float v = leaky(a_src[(size_t)s * 4 + myh] + ad_my);
        float w = expf(v - m_my) * inv_my;
        const float4* xp = (const float4*)(xs + (size_t)s * ldx + lane * 16);
        float4 x0 = xp[0], x1 = xp[1], x2 = xp[2], x3 = xp[3];
        acc0.x = fmaf(w, x0.x, acc0.x); acc0.y = fmaf(w, x0.y, acc0.y);
        acc0.z = fmaf(w, x0.z, acc0.z); acc0.w = fmaf(w, x0.w, acc0.w);
        acc1.x = fmaf(w, x1.x, acc1.x); acc1.y = fmaf(w, x1.y, acc1.y);
        acc1.z = fmaf(w, x1.z, acc1.z); acc1.w = fmaf(w, x1.w, acc1.w);
        acc2.x = fmaf(w, x2.x, acc2.x); acc2.y = fmaf(w, x2.y, acc2.y);
        acc2.z = fmaf(w, x2.z, acc2.z); acc2.w = fmaf(w, x2.w, acc2.w);
        acc3.x = fmaf(w, x3.x, acc3.x); acc3.y = fmaf(w, x3.y, acc3.y);
        acc3.z = fmaf(w, x3.z, acc3.z); acc3.w = fmaf(w, x3.w, acc3.w);
    }

    const float4* lp = (const float4*)(lin + (size_t)node * ldl + lane * 16);
    float4 l0 = lp[0], l1 = lp[1], l2 = lp[2], l3 = lp[3];
    float r[16];
    r[0]  = fmaxf(acc0.x + l0.x, 0.f); r[1]  = fmaxf(acc0.y + l0.y, 0.f);
    r[2]  = fmaxf(acc0.z + l0.z, 0.f); r[3]  = fmaxf(acc0.w + l0.w, 0.f);
    r[4]  = fmaxf(acc1.x + l1.x, 0.f); r[5]  = fmaxf(acc1.y + l1.y, 0.f);
    r[6]  = fmaxf(acc1.z + l1.z, 0.f); r[7]  = fmaxf(acc1.w + l1.w, 0.f);
    r[8]  = fmaxf(acc2.x + l2.x, 0.f); r[9]  = fmaxf(acc2.y + l2.y, 0.f);
    r[10] = fmaxf(acc2.z + l2.z, 0.f); r[11] = fmaxf(acc2.w + l2.w, 0.f);
    r[12] = fmaxf(acc3.x + l3.x, 0.f); r[13] = fmaxf(acc3.y + l3.y, 0.f);
    r[14] = fmaxf(acc3.z + l3.z, 0.f); r[15] = fmaxf(acc3.w + l3.w, 0.f);

    uint32_t hw[8], lw[8];
#pragma unroll
    for (int j = 0; j < 8; j++) {
        __nv_bfloat16 h0 = __float2bfloat16(r[2 * j]);
        __nv_bfloat16 h1 = __float2bfloat16(r[2 * j + 1]);
        hw[j] = ((uint32_t)(*(uint16_t*)&h1) << 16) | (*(uint16_t*)&h0);
        lw[j] = pack_bf16x2(r[2 * j]     - __bfloat162float(h0),
                            r[2 * j + 1] - __bfloat162float(h1));
    }
    const size_t tb = ((size_t)(node >> 7) * 16 + (lane >> 1)) * 8192;
    const uint32_t base = (uint32_t)((node & 127) * 64 + (lane & 1) * 32);
    const size_t o0 = tb + swz64(base);
    const size_t o1 = tb + swz64(base + 16);
    *(uint4*)(out_h + o0) = make_uint4(hw[0], hw[1], hw[2], hw[3]);
    *(uint4*)(out_h + o1) = make_uint4(hw[4], hw[5], hw[6], hw[7]);
    *(uint4*)(out_l + o0) = make_uint4(lw[0], lw[1], lw[2], lw[3]);
    *(uint4*)(out_l + o1) = make_uint4(lw[4], lw[5], lw[6], lw[7]);
}

// ---------------- host ----------------
static void tgemm(const void* Ah, const void* Al, int aChTot, int aChOff,
                  const void* Bh, const void* Bl, int bChTot,
                  float* C, int ldc,
                  void* Chi, void* Clo, int oChTot, int oColBase,
                  int M, int N, int Npad, int nchunks,
                  const float* b1, const float* b2, int relu)
{
    dim3 grid(Npad / 128, MTILES);
    tc_gemm<<<grid, GTHREADS, GEMM_SMEM>>>(
        (const char*)Ah, (const char*)Al, aChTot, aChOff,
        (const char*)Bh, (const char*)Bl, bChTot, C, ldc,
        (char*)Chi, (char*)Clo, oChTot, oColBase,
        M, N, nchunks, b1, b2, relu);
}

template <typename T>
static T* sym(T* s) { void* p = nullptr; cudaGetSymbolAddress(&p, (const void*)s); return (T*)p; }

extern "C" void kernel_launch(void* const* d_in, const int* in_sizes, int n_in,
                              void* d_out, int out_size)
{
    const float* x      = (const float*)d_in[0];
    const int*   ei     = (const int*)d_in[1];
    const float* W_rna  = (const float*)d_in[2];
    const float* b_rna  = (const float*)d_in[3];
    const float* W_prot = (const float*)d_in[4];
    const float* b_prot = (const float*)d_in[5];
    const float* g1_ws  = (const float*)d_in[6];
    const float* g1_wd  = (const float*)d_in[7];
    const float* g1_as  = (const float*)d_in[8];
    const float* g1_ad  = (const float*)d_in[9];
    const float* g1_b   = (const float*)d_in[10];
    const float* l1_w   = (const float*)d_in[11];
    const float* l1_b   = (const float*)d_in[12];
    const float* g2_ws  = (const float*)d_in[13];
    const float* g2_wd  = (const float*)d_in[14];
    const float* g2_as  = (const float*)d_in[15];
    const float* g2_ad  = (const float*)d_in[16];
    const float* g2_b   = (const float*)d_in[17];
    const float* l2_w   = (const float*)d_in[18];
    const float* l2_b   = (const float*)d_in[19];
    const float* agg_w  = (const float*)d_in[20];
    const float* agg_b  = (const float*)d_in[21];
    const float* dr_w   = (const float*)d_in[22];
    const float* dr_b   = (const float*)d_in[23];
    const float* dp_w   = (const float*)d_in[24];
    const float* dp_b   = (const float*)d_in[25];
    const float* rr_w   = (const float*)d_in[26];
    const float* rr_b   = (const float*)d_in[27];
    const float* rp_w   = (const float*)d_in[28];
    const float* rp_b   = (const float*)d_in[29];

    float* out = (float*)d_out;
    float* out_rna  = out;
    float* out_prot = out + (size_t)NN * RNA;
    float* out_emb  = out + (size_t)NN * (RNA + PROT);

    cudaFuncSetAttribute(tc_gemm, cudaFuncAttributeMaxDynamicSharedMemorySize, GEMM_SMEM);

    __nv_bfloat16 *xr_h = sym(g_xr_h), *xr_l = sym(g_xr_l);
    __nv_bfloat16 *xp_h = sym(g_xp_h), *xp_l = sym(g_xp_l);
    __nv_bfloat16 *hh = sym(g_hh), *hl = sym(g_hl);
    __nv_bfloat16 *eh = sym(g_eh), *el = sym(g_el);
    __nv_bfloat16 *rdh = sym(g_rdh), *rdl = sym(g_rdl);
    float *xslin = sym(g_xslin);
    float *asrc = sym(g_asrc), *adst = sym(g_adst);
    float *wp1 = sym(g_wp1), *wp2 = sym(g_wp2);
    float *bcat1 = sym(g_bcat1), *bcat2 = sym(g_bcat2), *bcatd = sym(g_bcatd);
    int *deg = sym(g_deg), *cur = sym(g_cursor), *rowptr = sym(g_rowptr), *csr = sym(g_csr);

    __nv_bfloat16 *wr_h = sym(g_wr_h), *wr_l = sym(g_wr_l);
    __nv_bfloat16 *wp_h = sym(g_wp_h), *wp_l = sym(g_wp_l);
    __nv_bfloat16 *wc1_h = sym(g_wc1_h), *wc1_l = sym(g_wc1_l);
    __nv_bfloat16 *wc2_h = sym(g_wc2_h), *wc2_l = sym(g_wc2_l);
    __nv_bfloat16 *wagg_h = sym(g_wagg_h), *wagg_l = sym(g_wagg_l);
    __nv_bfloat16 *wdc_h = sym(g_wdc_h), *wdc_l = sym(g_wdc_l);
    __nv_bfloat16 *wrr_h = sym(g_wrr_h), *wrr_l = sym(g_wrr_l);
    __nv_bfloat16 *wrp_h = sym(g_wrp_h), *wrp_l = sym(g_wrp_l);

    const int* e_src = ei;
    const int* e_dst = ei + EE;

    #define TSPLIT(W, K, N_, Kp, Np, H, L) \
        tsplit_kernel<<<(unsigned)(((long)(Np) * (Kp) + 255) / 256), 256>>>( \
            W, K, N_, Kp, Np, (char*)(H), (char*)(L))

    const int nAgg = (NN * 32 + 255) / 256;

    // CSR build first (independent of all GEMM work)
    zero2_kernel<<<(NN + 255) / 256, 256>>>(deg, cur, NN);
    count_kernel<<<(EE + 255) / 256, 256>>>(e_dst, deg, EE);
    scan_kernel<<<1, 1024>>>(deg, rowptr, NN);
    scatter_kernel<<<(EE + 255) / 256, 256>>>(e_src, e_dst, rowptr, cur, csr, EE);

    // weight prep
    TSPLIT(W_rna,  RNA,  EMB, 2048, 256, wr_h,  wr_l);
    TSPLIT(W_prot, PROT, EMB, 128,  256, wp_h,  wp_l);
    prep_layer_kernel<<<2052, 256>>>(g1_ws, l1_w, l1_b, g1_b,
                                     (char*)wc1_h, (char*)wc1_l, bcat1);

    // x split -> tiled hi/lo (once), then bulk embed GEMMs
    {
        long t1 = (long)MPAD * 64 * 8;
        splitx_kernel<<<(unsigned)((t1 + 255) / 256), 256>>>(
            x, INF, 0, NN, RNA, 64, (char*)xr_h, (char*)xr_l);
        long t2 = (long)MPAD * 4 * 8;
        splitx_kernel<<<(unsigned)((t2 + 255) / 256), 256>>>(
            x, INF, RNA, NN, PROT, 4, (char*)xp_h, (char*)xp_l);
    }
    tgemm(xr_h, xr_l, 64, 0, wr_h, wr_l, 64, nullptr, 0,
          hh, hl, 16, 0, NN, 256, 256, 63, b_rna, nullptr, 0);
    tgemm(xp_h, xp_l, 4, 0, wp_h, wp_l, 4, nullptr, 0,
          hh, hl, 16, 256, NN, 256, 256, 4, b_prot, nullptr, 0);

    // GAT layer 1 fused [xs|lin] GEMM (bulk)
    tgemm(hh, hl, 16, 0, wc1_h, wc1_l, 16, xslin, 1024,
          nullptr, nullptr, 0, 0, NN, 1024, 1024, 16, bcat1, nullptr, 0);
    wproj_kernel<<<2, 256>>>(g1_ws, g1_wd, g1_as, g1_ad, wp1);
    coef_kernel<<<nAgg, 256>>>((const char*)hh, (const char*)hl, wp1, asrc, adst);
    agg_kernel<<<nAgg, 256>>>(rowptr, csr, asrc, adst,
                              xslin, 1024, xslin + 512, 1024,
                              (char*)hh, (char*)hl);

    // GAT layer 2
    prep_layer_kernel<<<2052, 256>>>(g2_ws, l2_w, l2_b, g2_b,
                                     (char*)wc2_h, (char*)wc2_l, bcat2);
    tgemm(hh, hl, 16, 0, wc2_h, wc2_l, 16, xslin, 1024,
          nullptr, nullptr, 0, 0, NN, 1024, 1024, 16, bcat2, nullptr, 0);
    wproj_kernel<<<2, 256>>>(g2_ws, g2_wd, g2_as, g2_ad, wp2);
    coef_kernel<<<nAgg, 256>>>((const char*)hh, (const char*)hl, wp2, asrc, adst);
    agg_kernel<<<nAgg, 256>>>(rowptr, csr, asrc, adst,
                              xslin, 1024, xslin + 512, 1024,
                              (char*)hh, (char*)hl);

    // head: embedding
    TSPLIT(agg_w, HD, HID, 512, 128, wagg_h, wagg_l);
    tgemm(hh, hl, 16, 0, wagg_h, wagg_l, 16, out_emb, HID,
          eh, el, 4, 0, NN, HID, 128, 16, agg_b, nullptr, 1);

    // decoders (fused); dp_w tsplit + bias concat in one launch
    TSPLIT(dr_w, HID, EMB, 128, 256, wdc_h, wdc_l);
    tsplit_dec_kernel<<<130, 256>>>(dp_w, HID, EMB, 128, 256,
                                    (char*)wdc_h + 65536, (char*)wdc_l + 65536,
                                    dr_b, dp_b, bcatd);
    tgemm(eh, el, 4, 0, wdc_h, wdc_l, 4, nullptr, 0,
          rdh, rdl, 16, 0, NN, 512, 512, 4, bcatd, nullptr, 0);

    // reconstructions
    TSPLIT(rr_w, EMB, RNA, 256, 2048, wrr_h, wrr_l);
    tgemm(rdh, rdl, 16, 0, wrr_h, wrr_l, 8, out_rna, RNA,
          nullptr, nullptr, 0, 0, NN, RNA, 2048, 8, rr_b, nullptr, 0);
    TSPLIT(rp_w, EMB, PROT, 256, 128, wrp_h, wrp_l);
    tgemm(rdh, rdl, 16, 8, wrp_h, wrp_l, 8, out_prot, PROT,
          nullptr, nullptr, 0, 0, NN, PROT, 128, 8, rp_b, nullptr, 0);
}